// round 8
// baseline (speedup 1.0000x reference)
#include <cuda_runtime.h>
#include <cuda_bf16.h>
#include <cstdint>

#define Bc 2
#define Hc 16
#define Sc 2048
#define Dc 128
#define TOT (Bc*Hc*Sc*Dc)

#define BM 128
#define BN 128
#define NT 4            // nT tiles per CTA (persistent, K double-buffered)
#define LDT 136         // padded smem leading dim (bf16): 272B rows
#define TILE_B (BM*LDT*2)   // 34816 bytes per 128x128 bf16 tile

// Scratch (allocation-free rule: __device__ globals)
__device__ __nv_bfloat16 g_Qb[TOT];
__device__ __nv_bfloat16 g_Kb[TOT];
__device__ float g_pos[Bc*Sc];

// ---------------------------------------------------------------------------
// Prepass: q *= head_scale/sqrt(D) -> bf16 ; k -> bf16 ; gather positions
// ---------------------------------------------------------------------------
__global__ void prep_kernel(const float* __restrict__ q, const float* __restrict__ k,
                            const float* __restrict__ head_scales,
                            const float* __restrict__ positions,
                            const int* __restrict__ tok) {
    int tid = blockIdx.x * blockDim.x + threadIdx.x;
    int base = tid * 8;
    if (base < TOT) {
        int h = (base >> 18) & (Hc - 1);   // S*D = 2^18 elems per (b,h)
        float sc = head_scales[h] * 0.08838834764831845f; // 1/sqrt(128)

        float4 q0 = ((const float4*)q)[tid * 2];
        float4 q1 = ((const float4*)q)[tid * 2 + 1];
        __nv_bfloat162 qp[4];
        qp[0] = __floats2bfloat162_rn(q0.x * sc, q0.y * sc);
        qp[1] = __floats2bfloat162_rn(q0.z * sc, q0.w * sc);
        qp[2] = __floats2bfloat162_rn(q1.x * sc, q1.y * sc);
        qp[3] = __floats2bfloat162_rn(q1.z * sc, q1.w * sc);
        *(uint4*)(g_Qb + base) = *(uint4*)qp;

        float4 k0 = ((const float4*)k)[tid * 2];
        float4 k1 = ((const float4*)k)[tid * 2 + 1];
        __nv_bfloat162 kp[4];
        kp[0] = __floats2bfloat162_rn(k0.x, k0.y);
        kp[1] = __floats2bfloat162_rn(k0.z, k0.w);
        kp[2] = __floats2bfloat162_rn(k1.x, k1.y);
        kp[3] = __floats2bfloat162_rn(k1.z, k1.w);
        *(uint4*)(g_Kb + base) = *(uint4*)kp;
    }
    if (tid < Bc * Sc) {
        g_pos[tid] = positions[tok[tid]];
    }
}

// ---------------------------------------------------------------------------
// HMMA helpers
// ---------------------------------------------------------------------------
__device__ __forceinline__ void ldsm_x4(uint32_t addr, uint32_t* r) {
    asm volatile("ldmatrix.sync.aligned.m8n8.x4.shared.b16 {%0,%1,%2,%3}, [%4];\n"
                 : "=r"(r[0]), "=r"(r[1]), "=r"(r[2]), "=r"(r[3]) : "r"(addr));
}
__device__ __forceinline__ void mma_16816(float* c, const uint32_t* a, uint32_t b0, uint32_t b1) {
    asm volatile("mma.sync.aligned.m16n8k16.row.col.f32.bf16.bf16.f32 "
                 "{%0,%1,%2,%3}, {%4,%5,%6,%7}, {%8,%9}, {%0,%1,%2,%3};\n"
                 : "+f"(c[0]), "+f"(c[1]), "+f"(c[2]), "+f"(c[3])
                 : "r"(a[0]), "r"(a[1]), "r"(a[2]), "r"(a[3]), "r"(b0), "r"(b1));
}
__device__ __forceinline__ void cp16(uint32_t dst, const void* src) {
    asm volatile("cp.async.cg.shared.global [%0], [%1], 16;" :: "r"(dst), "l"(src));
}
#define CP_COMMIT() asm volatile("cp.async.commit_group;" ::: "memory")
#define CP_WAIT0()  asm volatile("cp.async.wait_group 0;" ::: "memory")

// ---------------------------------------------------------------------------
// Score kernel: per CTA fixed (z, mT); sweeps NT=4 K-tiles of 128 cols.
// Q staged once; K double-buffered via cp.async; fragments double-buffered in
// registers. Epilogue: bias fused at STS into the dead K buffer (XOR-swizzled
// 64x128 f32 scratch), then row-contiguous LDS.128 + STG.128 (128B/wavefront).
// ---------------------------------------------------------------------------
__global__ void __launch_bounds__(256, 2)
score_kernel(float* __restrict__ out, const float* __restrict__ slopes) {
    extern __shared__ char smem_raw[];
    __nv_bfloat16* qs  = (__nv_bfloat16*)smem_raw;                 // TILE_B
    __nv_bfloat16* ks0 = qs + BM * LDT;                            // 2x TILE_B
    float* rowPos = (float*)(smem_raw + 3 * TILE_B);               // 128 f
    float* colPosB = rowPos + BM;                                  // 2 x 128 f

    const int nT0 = blockIdx.x * NT;
    const int mT  = blockIdx.y;
    const int z   = blockIdx.z;           // b*H + h
    const int b   = z >> 4;
    const int h   = z & 15;
    const int t   = threadIdx.x;

    const uint32_t sq = (uint32_t)__cvta_generic_to_shared(qs);
    const uint32_t sk = (uint32_t)__cvta_generic_to_shared(ks0);

    const float slope = __ldg(slopes + h);
    const size_t zoff = (size_t)z * Sc * Dc;
    const __nv_bfloat16* Qg = g_Qb + zoff + (size_t)mT * BM * Dc;

    // Stage Q (once) + K tile 0, async
    #pragma unroll
    for (int i = t; i < BM * 16; i += 256) {
        int r = i >> 4, c = i & 15;
        cp16(sq + (uint32_t)(r * (LDT*2) + c * 16), Qg + r * Dc + c * 8);
    }
    {
        const __nv_bfloat16* Kg = g_Kb + zoff + (size_t)nT0 * BN * Dc;
        #pragma unroll
        for (int i = t; i < BN * 16; i += 256) {
            int r = i >> 4, c = i & 15;
            cp16(sk + (uint32_t)(r * (LDT*2) + c * 16), Kg + r * Dc + c * 8);
        }
    }
    CP_COMMIT();

    if (t < BM)       rowPos[t]        = g_pos[b * Sc + mT * BM + t] * slope;
    else              colPosB[t - BM]  = g_pos[b * Sc + nT0 * BN + (t - BM)] * slope; // buf 0

    CP_WAIT0();
    __syncthreads();

    const int lane = t & 31, wid = t >> 5;
    const int wm = (wid & 3) * 32;   // warp m offset
    const int wn = (wid >> 2) * 64;  // warp n offset
    const int lr = lane & 15;
    const int lc = (lane >> 4) * 8;
    const int qr0 = lane >> 2;
    const int cc0 = (lane & 3) * 2;

    // Precomputed ldsm base addresses
    uint32_t aAddr[2], bOff[4];
    #pragma unroll
    for (int im = 0; im < 2; im++)
        aAddr[im] = sq + (uint32_t)(((wm + im * 16 + lr) * LDT + lc) * 2);
    #pragma unroll
    for (int in2 = 0; in2 < 4; in2++)
        bOff[in2] = (uint32_t)(((wn + in2 * 16 + lr) * LDT + lc) * 2);

    const size_t outBase = (size_t)z * Sc * Sc;

    for (int it = 0; it < NT; it++) {
        const int cur = it & 1, nxt = cur ^ 1;
        const uint32_t kb = sk + (uint32_t)cur * TILE_B;

        // Prefetch next K tile + next colPos into the other buffer
        if (it < NT - 1) {
            const __nv_bfloat16* Kg = g_Kb + zoff + (size_t)(nT0 + it + 1) * BN * Dc;
            #pragma unroll
            for (int i = t; i < BN * 16; i += 256) {
                int r = i >> 4, c = i & 15;
                cp16(sk + (uint32_t)(nxt * TILE_B + r * (LDT*2) + c * 16), Kg + r * Dc + c * 8);
            }
            CP_COMMIT();
            if (t < BN)
                colPosB[nxt * BN + t] = g_pos[b * Sc + (nT0 + it + 1) * BN + t] * slope;
        }

        // ---- compute 128x128 tile, register-double-buffered fragments ----
        float acc[2][8][4];
        #pragma unroll
        for (int im = 0; im < 2; im++)
            #pragma unroll
            for (int in = 0; in < 8; in++)
                #pragma unroll
                for (int r = 0; r < 4; r++) acc[im][in][r] = 0.0f;

        uint32_t a[2][2][4];   // [buf][im][reg]
        uint32_t brf[2][4][4]; // [buf][in2][reg]

        #pragma unroll
        for (int im = 0; im < 2; im++) ldsm_x4(aAddr[im], a[0][im]);
        #pragma unroll
        for (int in2 = 0; in2 < 4; in2++) ldsm_x4(kb + bOff[in2], brf[0][in2]);

        #pragma unroll
        for (int kk = 0; kk < 8; kk++) {
            const int fc = kk & 1, fn = fc ^ 1;
            if (kk < 7) {
                const uint32_t ko = (uint32_t)((kk + 1) * 32); // 16 bf16 = 32B
                #pragma unroll
                for (int im = 0; im < 2; im++) ldsm_x4(aAddr[im] + ko, a[fn][im]);
                #pragma unroll
                for (int in2 = 0; in2 < 4; in2++) ldsm_x4(kb + bOff[in2] + ko, brf[fn][in2]);
            }
            #pragma unroll
            for (int im = 0; im < 2; im++)
                #pragma unroll
                for (int in = 0; in < 8; in++) {
                    int in2 = in >> 1, sub = in & 1;
                    mma_16816(acc[im][in], a[fc][im], brf[fc][in2][sub], brf[fc][in2][sub + 2]);
                }
        }

        __syncthreads();   // all warps done reading cur K tile -> reuse as scratch

        // ---- epilogue: bias at STS into swizzled scratch, coalesced STG ----
        // scratch: 64 rows x 128 f32 (32KB) inside the dead cur K buffer.
        float* scratch = (float*)(smem_raw + TILE_B + cur * TILE_B);
        const float* cp = colPosB + cur * BN;
        const int myPass = (wm >> 6) & 1;            // rows 0-63 or 64-127

        #pragma unroll
        for (int p = 0; p < 2; p++) {
            if (myPass == p) {
                const int lrB = wm & 63;             // 0 or 32
                #pragma unroll
                for (int im = 0; im < 2; im++) {
                    const int gr = wm + im * 16 + qr0;
                    const float prA = rowPos[gr];
                    const float prB = rowPos[gr + 8];
                    const int lr0 = lrB + im * 16 + qr0;
                    #pragma unroll
                    for (int in = 0; in < 8; in++) {
                        const int col = wn + in * 8 + cc0;
                        const int sw  = col ^ (qr0 << 3);   // XOR swizzle by row&7
                        const float pc0 = cp[col];
                        const float pc1 = cp[col + 1];
                        float2 v0, v1;
                        v0.x = acc[im][in][0] - prA + pc0;
                        v0.y = acc[im][in][1] - prA + pc1;
                        v1.x = acc[im][in][2] - prB + pc0;
                        v1.y = acc[im][in][3] - prB + pc1;
                        *(float2*)(scratch + lr0 * 128 + sw)       = v0;
                        *(float2*)(scratch + (lr0 + 8) * 128 + sw) = v1;
                    }
                }
            }
            __syncthreads();
            // All 8 warps: rows wid*8 .. wid*8+7, row-contiguous stores
            #pragma unroll
            for (int rr = 0; rr < 8; rr++) {
                const int lrow = wid * 8 + rr;
                const int sw = (4 * lane) ^ ((lrow & 7) << 3);
                float4 v = *(const float4*)(scratch + lrow * 128 + sw);
                const size_t gRow = (size_t)(mT * BM + p * 64 + lrow);
                *(float4*)(out + outBase + gRow * Sc + (size_t)(nT0 + it) * BN + 4 * lane) = v;
            }
            if (p == 0) __syncthreads();   // before pass-1 STS overwrites scratch
        }

        if (it < NT - 1) {
            CP_WAIT0();
            __syncthreads();
        }
    }
}

// ---------------------------------------------------------------------------
extern "C" void kernel_launch(void* const* d_in, const int* in_sizes, int n_in,
                              void* d_out, int out_size) {
    const float* q         = (const float*)d_in[0];
    const float* k         = (const float*)d_in[1];
    const float* hs        = (const float*)d_in[2];
    const float* slopes    = (const float*)d_in[3];
    const float* positions = (const float*)d_in[4];
    const int*   tok       = (const int*)d_in[5];
    float* out = (float*)d_out;

    prep_kernel<<<TOT / 8 / 256, 256>>>(q, k, hs, positions, tok);

    const int smem_bytes = 3 * TILE_B + (BM + 2 * BN) * 4;
    cudaFuncSetAttribute(score_kernel, cudaFuncAttributeMaxDynamicSharedMemorySize, smem_bytes);
    dim3 grid(Sc / BN / NT, Sc / BM, Bc * Hc);
    score_kernel<<<grid, 256, smem_bytes>>>(out, slopes);
}

// round 10
// speedup vs baseline: 1.2100x; 1.2100x over previous
#include <cuda_runtime.h>
#include <cuda_bf16.h>
#include <cstdint>

#define Bc 2
#define Hc 16
#define Sc 2048
#define Dc 128
#define TOT (Bc*Hc*Sc*Dc)

#define BM 128
#define BN 128
#define NT 4                  // K tiles per CTA (persistent, double-buffered)
#define TILE_B (BM*Dc*2)      // 32768 B, linear (gmem-pre-swizzled) tile

// SMEM byte offsets
#define SM_Q     0
#define SM_K     32768        // 2 buffers
#define SM_RPOS  98304        // 128 floats
#define SM_CPOS  98816        // 2 x 128 floats
#define SM_MBAR0 99840
#define SM_MBAR1 99848
#define SM_TOTAL 99856

// Scratch (allocation-free rule: __device__ globals)
__device__ __nv_bfloat16 g_Qb[TOT];
__device__ __nv_bfloat16 g_Kb[TOT];
__device__ float g_pos[Bc*Sc];

// ---------------------------------------------------------------------------
// Prepass: q *= head_scale/sqrt(D) -> bf16 ; k -> bf16 ; gather positions.
// Rows are stored PRE-SWIZZLED: 16B chunk c of row r lands at chunk c^(r&7),
// so a linear bulk-copied smem tile is ldmatrix-conflict-free.
// ---------------------------------------------------------------------------
__global__ void prep_kernel(const float* __restrict__ q, const float* __restrict__ k,
                            const float* __restrict__ head_scales,
                            const float* __restrict__ positions,
                            const int* __restrict__ tok) {
    int tid = blockIdx.x * blockDim.x + threadIdx.x;
    int base = tid * 8;                       // one 16B chunk (8 bf16)
    if (base < TOT) {
        int h = (base >> 18) & (Hc - 1);      // S*D = 2^18 elems per (b,h)
        float sc = head_scales[h] * 0.08838834764831845f; // 1/sqrt(128)

        int r = base >> 7;                    // global row (128 elems/row)
        int c = (base >> 3) & 15;             // chunk within row
        int dst = (r << 7) + ((c ^ (r & 7)) << 3);

        float4 q0 = ((const float4*)q)[tid * 2];
        float4 q1 = ((const float4*)q)[tid * 2 + 1];
        __nv_bfloat162 qp[4];
        qp[0] = __floats2bfloat162_rn(q0.x * sc, q0.y * sc);
        qp[1] = __floats2bfloat162_rn(q0.z * sc, q0.w * sc);
        qp[2] = __floats2bfloat162_rn(q1.x * sc, q1.y * sc);
        qp[3] = __floats2bfloat162_rn(q1.z * sc, q1.w * sc);
        *(uint4*)(g_Qb + dst) = *(uint4*)qp;

        float4 k0 = ((const float4*)k)[tid * 2];
        float4 k1 = ((const float4*)k)[tid * 2 + 1];
        __nv_bfloat162 kp[4];
        kp[0] = __floats2bfloat162_rn(k0.x, k0.y);
        kp[1] = __floats2bfloat162_rn(k0.z, k0.w);
        kp[2] = __floats2bfloat162_rn(k1.x, k1.y);
        kp[3] = __floats2bfloat162_rn(k1.z, k1.w);
        *(uint4*)(g_Kb + dst) = *(uint4*)kp;
    }
    if (tid < Bc * Sc) {
        g_pos[tid] = positions[tok[tid]];
    }
}

// ---------------------------------------------------------------------------
// Helpers
// ---------------------------------------------------------------------------
__device__ __forceinline__ void ldsm_x4(uint32_t addr, uint32_t* r) {
    asm volatile("ldmatrix.sync.aligned.m8n8.x4.shared.b16 {%0,%1,%2,%3}, [%4];\n"
                 : "=r"(r[0]), "=r"(r[1]), "=r"(r[2]), "=r"(r[3]) : "r"(addr));
}
__device__ __forceinline__ void mma_16816(float* c, const uint32_t* a, uint32_t b0, uint32_t b1) {
    asm volatile("mma.sync.aligned.m16n8k16.row.col.f32.bf16.bf16.f32 "
                 "{%0,%1,%2,%3}, {%4,%5,%6,%7}, {%8,%9}, {%0,%1,%2,%3};\n"
                 : "+f"(c[0]), "+f"(c[1]), "+f"(c[2]), "+f"(c[3])
                 : "r"(a[0]), "r"(a[1]), "r"(a[2]), "r"(a[3]), "r"(b0), "r"(b1));
}
__device__ __forceinline__ void mbar_init(uint32_t mbar, uint32_t cnt) {
    asm volatile("mbarrier.init.shared.b64 [%0], %1;" :: "r"(mbar), "r"(cnt) : "memory");
}
__device__ __forceinline__ void mbar_expect(uint32_t mbar, uint32_t bytes) {
    asm volatile("mbarrier.arrive.expect_tx.shared.b64 _, [%0], %1;"
                 :: "r"(mbar), "r"(bytes) : "memory");
}
__device__ __forceinline__ void bulk_g2s(uint32_t dst, const void* src, uint32_t bytes, uint32_t mbar) {
    asm volatile("cp.async.bulk.shared::cta.global.mbarrier::complete_tx::bytes "
                 "[%0], [%1], %2, [%3];"
                 :: "r"(dst), "l"(src), "r"(bytes), "r"(mbar) : "memory");
}
__device__ __forceinline__ void mbar_wait(uint32_t mbar, uint32_t parity) {
    uint32_t done;
    asm volatile(
        "{\n\t.reg .pred p;\n\t"
        "mbarrier.try_wait.parity.acquire.cta.shared::cta.b64 p, [%1], %2;\n\t"
        "selp.b32 %0, 1, 0, p;\n\t}"
        : "=r"(done) : "r"(mbar), "r"(parity) : "memory");
    if (!done) {
        asm volatile(
            "{\n\t.reg .pred P1;\n\t"
            "WL_%=:\n\t"
            "mbarrier.try_wait.parity.acquire.cta.shared::cta.b64 P1, [%0], %1, 0x989680;\n\t"
            "@P1 bra.uni WD_%=;\n\t"
            "bra.uni WL_%=;\n\t"
            "WD_%=:\n\t}"
            :: "r"(mbar), "r"(parity) : "memory");
    }
}

// ---------------------------------------------------------------------------
// Score kernel: per CTA fixed (z, mT); sweeps NT=4 K-tiles of 128 cols.
// Tiles staged by cp.async.bulk (TMA, zero LSU cost); data pre-swizzled in
// gmem so linear copies are ldmatrix-conflict-free. Frags reg-double-buffered.
// 8 warps, warp tile 32x64, 2 CTAs/SM.
// ---------------------------------------------------------------------------
__global__ void __launch_bounds__(256, 2)
score_kernel(float* __restrict__ out, const float* __restrict__ slopes) {
    extern __shared__ char smem_raw[];
    const uint32_t sb = (uint32_t)__cvta_generic_to_shared(smem_raw);
    float* rowPos  = (float*)(smem_raw + SM_RPOS);
    float* colPosB = (float*)(smem_raw + SM_CPOS);

    const int nT0 = blockIdx.x * NT;
    const int mT  = blockIdx.y;
    const int z   = blockIdx.z;           // b*H + h
    const int b   = z >> 4;
    const int h   = z & 15;
    const int t   = threadIdx.x;

    const float slope = __ldg(slopes + h);
    const size_t zoff = (size_t)z * Sc * Dc;

    if (t == 0) {
        mbar_init(sb + SM_MBAR0, 1);
        mbar_init(sb + SM_MBAR1, 1);
    }
    __syncthreads();

    if (t == 0) {
        mbar_expect(sb + SM_MBAR0, 2 * TILE_B);
        bulk_g2s(sb + SM_Q, g_Qb + zoff + (size_t)mT * BM * Dc, TILE_B, sb + SM_MBAR0);
        bulk_g2s(sb + SM_K, g_Kb + zoff + (size_t)nT0 * BN * Dc, TILE_B, sb + SM_MBAR0);
    }

    if (t < BM)       rowPos[t]       = g_pos[b * Sc + mT * BM + t] * slope;
    else              colPosB[t - BM] = g_pos[b * Sc + nT0 * BN + (t - BM)] * slope; // buf 0
    __syncthreads();

    const int lane = t & 31, wid = t >> 5;
    const int wm = (wid & 3) * 32;   // warp m offset
    const int wn = (wid >> 2) * 64;  // warp n offset
    const int lr = lane & 15;
    const int hsel = lane >> 4;      // chunk half-select (0/1)
    const int x  = lr & 7;           // swizzle key (row & 7)
    const int qr0 = lane >> 2;
    const int cc0 = (lane & 3) * 2;

    // Row base addresses (256B row stride, linear tiles)
    uint32_t aBase[2];
    #pragma unroll
    for (int im = 0; im < 2; im++)
        aBase[im] = sb + SM_Q + (uint32_t)((wm + im * 16 + lr) << 8);
    uint32_t bRow[4];
    #pragma unroll
    for (int in2 = 0; in2 < 4; in2++)
        bRow[in2] = (uint32_t)((wn + in2 * 16 + lr) << 8);

    const size_t outBase = (size_t)z * Sc * Sc;

    for (int it = 0; it < NT; it++) {
        const int cur = it & 1, nxt = cur ^ 1;
        const uint32_t kb = sb + SM_K + (uint32_t)cur * TILE_B;

        // Prefetch next K tile (TMA) + next colPos into the other buffer
        if (it < NT - 1) {
            if (t == 0) {
                const uint32_t mb = sb + (nxt ? SM_MBAR1 : SM_MBAR0);
                mbar_expect(mb, TILE_B);
                bulk_g2s(sb + SM_K + (uint32_t)nxt * TILE_B,
                         g_Kb + zoff + (size_t)(nT0 + it + 1) * BN * Dc, TILE_B, mb);
            }
            if (t < BN)
                colPosB[nxt * BN + t] = g_pos[b * Sc + (nT0 + it + 1) * BN + t] * slope;
        }

        // Wait for current tile(s): mbar[it&1], parity (it>>1)&1
        mbar_wait(sb + (cur ? SM_MBAR1 : SM_MBAR0), (it >> 1) & 1);

        // ---- compute 128x128 tile, register-double-buffered fragments ----
        float acc[2][8][4];
        #pragma unroll
        for (int im = 0; im < 2; im++)
            #pragma unroll
            for (int in = 0; in < 8; in++)
                #pragma unroll
                for (int r = 0; r < 4; r++) acc[im][in][r] = 0.0f;

        uint32_t a[2][2][4];   // [buf][im][reg]
        uint32_t brf[2][4][4]; // [buf][in2][reg]

        // k-step chunk offset with swizzle: ((2*kk + hsel) ^ x) * 16
        #pragma unroll
        for (int im = 0; im < 2; im++)
            ldsm_x4(aBase[im] + (uint32_t)(((hsel ^ x) << 4)), a[0][im]);
        #pragma unroll
        for (int in2 = 0; in2 < 4; in2++)
            ldsm_x4(kb + bRow[in2] + (uint32_t)(((hsel ^ x) << 4)), brf[0][in2]);

        #pragma unroll
        for (int kk = 0; kk < 8; kk++) {
            const int fc = kk & 1, fn = fc ^ 1;
            if (kk < 7) {
                const uint32_t ko = (uint32_t)((((2 * (kk + 1) + hsel) ^ x)) << 4);
                #pragma unroll
                for (int im = 0; im < 2; im++) ldsm_x4(aBase[im] + ko, a[fn][im]);
                #pragma unroll
                for (int in2 = 0; in2 < 4; in2++) ldsm_x4(kb + bRow[in2] + ko, brf[fn][in2]);
            }
            #pragma unroll
            for (int im = 0; im < 2; im++)
                #pragma unroll
                for (int in = 0; in < 8; in++) {
                    int in2 = in >> 1, sub = in & 1;
                    mma_16816(acc[im][in], a[fc][im], brf[fc][in2][sub], brf[fc][in2][sub + 2]);
                }
        }

        // ---- epilogue: out = score - slope*pos_q + slope*pos_k ----
        const float* cp = colPosB + cur * BN;
        #pragma unroll
        for (int im = 0; im < 2; im++) {
            const int rA = wm + im * 16 + qr0;
            const float prA = rowPos[rA];
            const float prB = rowPos[rA + 8];
            const size_t gRowA = (size_t)(mT * BM + rA);
            float* oA = out + outBase + gRowA * Sc + (size_t)(nT0 + it) * BN;
            float* oB = oA + 8 * Sc;
            #pragma unroll
            for (int in = 0; in < 8; in++) {
                const int cl = wn + in * 8 + cc0;
                const float pc0 = cp[cl];
                const float pc1 = cp[cl + 1];
                float2 v0, v1;
                v0.x = acc[im][in][0] - prA + pc0;
                v0.y = acc[im][in][1] - prA + pc1;
                v1.x = acc[im][in][2] - prB + pc0;
                v1.y = acc[im][in][3] - prB + pc1;
                *(float2*)(oA + cl) = v0;
                *(float2*)(oB + cl) = v1;
            }
        }

        // Guard K-buffer reuse and colPos visibility
        if (it < NT - 1) __syncthreads();
    }
}

// ---------------------------------------------------------------------------
extern "C" void kernel_launch(void* const* d_in, const int* in_sizes, int n_in,
                              void* d_out, int out_size) {
    const float* q         = (const float*)d_in[0];
    const float* k         = (const float*)d_in[1];
    const float* hs        = (const float*)d_in[2];
    const float* slopes    = (const float*)d_in[3];
    const float* positions = (const float*)d_in[4];
    const int*   tok       = (const int*)d_in[5];
    float* out = (float*)d_out;

    prep_kernel<<<TOT / 8 / 256, 256>>>(q, k, hs, positions, tok);

    cudaFuncSetAttribute(score_kernel, cudaFuncAttributeMaxDynamicSharedMemorySize, SM_TOTAL);
    dim3 grid(Sc / BN / NT, Sc / BM, Bc * Hc);
    score_kernel<<<grid, 256, SM_TOTAL>>>(out, slopes);
}